// round 1
// baseline (speedup 1.0000x reference)
#include <cuda_runtime.h>
#include <cuda_bf16.h>
#include <math.h>

// Problem dims
#define TT   512
#define BB   64
#define II   1024
#define HH   1024
#define N4H  4096   // 4*H
#define MTOT (TT*BB)        // 32768

// Scratch (allocation-free per harness rules)
__device__ float g_xp[(size_t)MTOT * N4H];  // precomputed input projections + bias, [m][4H]
__device__ float g_c[BB * HH];              // cell state

// ---------------------------------------------------------------------------
// Kernel 1: input projection  g_xp[m][g*H+j] = b_g[j] + sum_k X[m][k]*Wg_i[j][k]
// Classic 128x128x8 SGEMM, 256 threads, 8x8 microtile, register prefetch.
// ---------------------------------------------------------------------------
__global__ __launch_bounds__(256) void proj_kernel(
    const float* __restrict__ X,
    const float* __restrict__ wi0, const float* __restrict__ wi1,
    const float* __restrict__ wi2, const float* __restrict__ wi3,
    const float* __restrict__ bi0, const float* __restrict__ bi1,
    const float* __restrict__ bi2, const float* __restrict__ bi3)
{
    __shared__ float A_sh[8][128];
    __shared__ float B_sh[8][128];

    const int tid = threadIdx.x;
    const int n0  = blockIdx.x * 128;      // column tile (within one gate: 1024%128==0)
    const int m0  = blockIdx.y * 128;      // row tile
    const int gate = n0 >> 10;
    const int j0   = n0 & 1023;

    const float* wsel = (gate == 0) ? wi0 : (gate == 1) ? wi1 : (gate == 2) ? wi2 : wi3;
    const float* bsel = (gate == 0) ? bi0 : (gate == 1) ? bi1 : (gate == 2) ? bi2 : bi3;

    const int lm = tid >> 1;               // 0..127
    const int lk = (tid & 1) * 4;          // 0 or 4

    const float* aptr = X    + (size_t)(m0 + lm) * II + lk;
    const float* bptr = wsel + (size_t)(j0 + lm) * II + lk;

    float4 aReg = *(const float4*)aptr;
    float4 bReg = *(const float4*)bptr;

    const int tx = tid & 15;               // 0..15 -> cols tx*8..tx*8+7
    const int ty = tid >> 4;               // 0..15 -> rows ty*8..ty*8+7

    float acc[8][8];
#pragma unroll
    for (int i = 0; i < 8; i++)
#pragma unroll
        for (int j = 0; j < 8; j++) acc[i][j] = 0.f;

    for (int kt = 0; kt < II; kt += 8) {
        A_sh[lk + 0][lm] = aReg.x; A_sh[lk + 1][lm] = aReg.y;
        A_sh[lk + 2][lm] = aReg.z; A_sh[lk + 3][lm] = aReg.w;
        B_sh[lk + 0][lm] = bReg.x; B_sh[lk + 1][lm] = bReg.y;
        B_sh[lk + 2][lm] = bReg.z; B_sh[lk + 3][lm] = bReg.w;
        __syncthreads();

        if (kt + 8 < II) {                 // prefetch next tile while computing
            aReg = *(const float4*)(aptr + kt + 8);
            bReg = *(const float4*)(bptr + kt + 8);
        }

#pragma unroll
        for (int k = 0; k < 8; k++) {
            float4 a0 = *(const float4*)&A_sh[k][ty * 8];
            float4 a1 = *(const float4*)&A_sh[k][ty * 8 + 4];
            float4 c0 = *(const float4*)&B_sh[k][tx * 8];
            float4 c1 = *(const float4*)&B_sh[k][tx * 8 + 4];
            float av[8] = {a0.x, a0.y, a0.z, a0.w, a1.x, a1.y, a1.z, a1.w};
            float bv[8] = {c0.x, c0.y, c0.z, c0.w, c1.x, c1.y, c1.z, c1.w};
#pragma unroll
            for (int i = 0; i < 8; i++)
#pragma unroll
                for (int j = 0; j < 8; j++) acc[i][j] += av[i] * bv[j];
        }
        __syncthreads();
    }

    // bias + store
    float bb[8];
#pragma unroll
    for (int j = 0; j < 8; j++) bb[j] = bsel[j0 + tx * 8 + j];

#pragma unroll
    for (int i = 0; i < 8; i++) {
        size_t row = (size_t)(m0 + ty * 8 + i) * N4H + n0 + tx * 8;
        float4 v0 = make_float4(acc[i][0] + bb[0], acc[i][1] + bb[1],
                                acc[i][2] + bb[2], acc[i][3] + bb[3]);
        float4 v1 = make_float4(acc[i][4] + bb[4], acc[i][5] + bb[5],
                                acc[i][6] + bb[6], acc[i][7] + bb[7]);
        *(float4*)&g_xp[row]     = v0;
        *(float4*)&g_xp[row + 4] = v1;
    }
}

// ---------------------------------------------------------------------------
// Kernel 2: one recurrent step.
// Block owns j in [j0, j0+8) x all 4 gates x all 64 batches.
// Thread: jj = tid&7, bq = tid>>3 -> batches {bq, bq+32}, acc[2][4].
// Epilogue fuses gate activations + cell/hidden update (block has all 4 gates).
// ---------------------------------------------------------------------------
__device__ __forceinline__ float sigmoidf_(float x) { return 1.f / (1.f + expf(-x)); }

__global__ __launch_bounds__(256) void step_kernel(
    int t,
    const float* __restrict__ hx, const float* __restrict__ cx,
    float* __restrict__ out,
    const float* __restrict__ wh0, const float* __restrict__ wh1,
    const float* __restrict__ wh2, const float* __restrict__ wh3)
{
    const float* hprev = (t == 0) ? hx : out + (size_t)(t - 1) * (BB * HH);
    const float* cprev = (t == 0) ? cx : g_c;
    float*       hout  = out + (size_t)t * (BB * HH);
    const float* xp    = g_xp + (size_t)t * BB * N4H;

    __shared__ float h_sh[64][36];        // [b][k], pad to 36 (144B rows, 16B-aligned float4)
    __shared__ float w_sh[4][8][36];      // [gate][j][k]

    const int tid = threadIdx.x;
    const int j0  = blockIdx.x * 8;

    // global-load mapping
    const int hr = tid >> 2;              // 0..63  (batch row)
    const int hk = (tid & 3) * 8;         // 8 k's per thread
    const int wg = tid >> 6;              // 0..3   (gate)
    const int wj = (tid >> 3) & 7;        // 0..7   (j within block)
    const int wk = (tid & 7) * 4;         // 4 k's per thread

    const float* wsel = (wg == 0) ? wh0 : (wg == 1) ? wh1 : (wg == 2) ? wh2 : wh3;
    const float* hsrc = hprev + (size_t)hr * HH + hk;
    const float* wsrc = wsel  + (size_t)(j0 + wj) * HH + wk;

    float4 hA = *(const float4*)hsrc;
    float4 hB = *(const float4*)(hsrc + 4);
    float4 wA = *(const float4*)wsrc;

    const int jj = tid & 7;
    const int bq = tid >> 3;              // 0..31

    float acc[2][4];
#pragma unroll
    for (int p = 0; p < 2; p++)
#pragma unroll
        for (int g = 0; g < 4; g++) acc[p][g] = 0.f;

    for (int kt = 0; kt < HH; kt += 32) {
        *(float4*)&h_sh[hr][hk]     = hA;
        *(float4*)&h_sh[hr][hk + 4] = hB;
        *(float4*)&w_sh[wg][wj][wk] = wA;
        __syncthreads();

        if (kt + 32 < HH) {               // prefetch next tile
            hA = *(const float4*)(hsrc + kt + 32);
            hB = *(const float4*)(hsrc + kt + 36);
            wA = *(const float4*)(wsrc + kt + 32);
        }

#pragma unroll
        for (int kk = 0; kk < 32; kk += 4) {
            float4 h0 = *(const float4*)&h_sh[bq][kk];
            float4 h1 = *(const float4*)&h_sh[bq + 32][kk];
#pragma unroll
            for (int g = 0; g < 4; g++) {
                float4 wv = *(const float4*)&w_sh[g][jj][kk];
                acc[0][g] += h0.x * wv.x; acc[0][g] += h0.y * wv.y;
                acc[0][g] += h0.z * wv.z; acc[0][g] += h0.w * wv.w;
                acc[1][g] += h1.x * wv.x; acc[1][g] += h1.y * wv.y;
                acc[1][g] += h1.z * wv.z; acc[1][g] += h1.w * wv.w;
            }
        }
        __syncthreads();
    }

    // fused epilogue: gates -> activations -> cell/hidden update
#pragma unroll
    for (int p = 0; p < 2; p++) {
        const int b = bq + 32 * p;
        const int j = j0 + jj;
        const float* xpb = xp + (size_t)b * N4H + j;
        float gi = acc[p][0] + xpb[0];
        float gf = acc[p][1] + xpb[1024];
        float ga = acc[p][2] + xpb[2048];
        float go = acc[p][3] + xpb[3072];
        float ig = sigmoidf_(gi);
        float fg = sigmoidf_(gf);
        float ag = tanhf(ga);
        float og = sigmoidf_(go);
        float c  = fg * cprev[(size_t)b * HH + j] + ig * ag;
        g_c[b * HH + j]  = c;
        hout[b * HH + j] = og * tanhf(c);
    }
}

// ---------------------------------------------------------------------------
// Kernel 3: hy = outputs[T-1], cy = final cell state
// ---------------------------------------------------------------------------
__global__ void finalize_kernel(float* __restrict__ out)
{
    int i = blockIdx.x * blockDim.x + threadIdx.x;   // 0..65535
    const size_t TBH = (size_t)TT * BB * HH;
    out[TBH + i]                 = out[TBH - (size_t)BB * HH + i];  // hy
    out[TBH + (size_t)BB * HH + i] = g_c[i];                        // cy
}

// ---------------------------------------------------------------------------
extern "C" void kernel_launch(void* const* d_in, const int* in_sizes, int n_in,
                              void* d_out, int out_size)
{
    const float* X    = (const float*)d_in[0];
    const float* hx   = (const float*)d_in[1];
    const float* cx   = (const float*)d_in[2];
    const float* w_ii = (const float*)d_in[3];
    const float* w_fi = (const float*)d_in[4];
    const float* w_ai = (const float*)d_in[5];
    const float* w_oi = (const float*)d_in[6];
    const float* w_ih = (const float*)d_in[7];
    const float* w_fh = (const float*)d_in[8];
    const float* w_ah = (const float*)d_in[9];
    const float* w_oh = (const float*)d_in[10];
    const float* b_i  = (const float*)d_in[11];
    const float* b_f  = (const float*)d_in[12];
    const float* b_a  = (const float*)d_in[13];
    const float* b_o  = (const float*)d_in[14];
    float* out = (float*)d_out;

    (void)in_sizes; (void)n_in; (void)out_size;

    // Phase 1: all input projections in one big GEMM (no recurrence dependency)
    dim3 pg(N4H / 128, MTOT / 128);   // (32, 256)
    proj_kernel<<<pg, 256>>>(X, w_ii, w_fi, w_ai, w_oi, b_i, b_f, b_a, b_o);

    // Phase 2: 512 sequential recurrent steps
    for (int t = 0; t < TT; t++) {
        step_kernel<<<128, 256>>>(t, hx, cx, out, w_ih, w_fh, w_ah, w_oh);
    }

    // Phase 3: hy / cy tail
    finalize_kernel<<<(BB * HH) / 256, 256>>>(out);
}

// round 3
// speedup vs baseline: 1.4715x; 1.4715x over previous
#include <cuda_runtime.h>
#include <cuda_bf16.h>
#include <math.h>
#include <stdint.h>

// Problem dims
#define TT   512
#define BB   64
#define II   1024
#define HH   1024
#define N4H  4096
#define MTOT (TT*BB)        // 32768

// Step-kernel tiling
#define NCTA    128         // CTAs per step
#define NPC     32          // gate-output columns (p) per CTA
#define KCHUNK  64          // bf16 K elements per chunk (128B rows)
#define NCHUNK  (HH/KCHUNK) // 16

// ---------------------------------------------------------------------------
// Device scratch (allocation-free)
// ---------------------------------------------------------------------------
__device__ float g_xp[(size_t)MTOT * N4H];        // input projections + bias, p-ordered cols
__device__ float g_c[BB * HH];                    // cell state
__device__ __nv_bfloat16 g_whi[(size_t)N4H * HH]; // Wh hi, row p = j*4+gate
__device__ __nv_bfloat16 g_wlo[(size_t)N4H * HH]; // Wh lo
__device__ __nv_bfloat16 g_hhi[2][BB * HH];       // h hi, ping-pong by t
__device__ __nv_bfloat16 g_hlo[2][BB * HH];       // h lo

// ---------------------------------------------------------------------------
// Helpers
// ---------------------------------------------------------------------------
__device__ __forceinline__ uint32_t smem_u32(const void* p) {
    uint32_t a;
    asm("{ .reg .u64 t; cvta.to.shared.u64 t, %1; cvt.u32.u64 %0, t; }" : "=r"(a) : "l"(p));
    return a;
}
__device__ __forceinline__ void cp_async16(uint32_t smem_addr, const void* gptr) {
    asm volatile("cp.async.cg.shared.global [%0], [%1], 16;" :: "r"(smem_addr), "l"(gptr));
}
#define CP_COMMIT() asm volatile("cp.async.commit_group;" ::: "memory")

__device__ __forceinline__ void ldsm4(uint32_t* r, uint32_t addr) {
    asm volatile("ldmatrix.sync.aligned.m8n8.x4.shared.b16 {%0,%1,%2,%3}, [%4];"
                 : "=r"(r[0]), "=r"(r[1]), "=r"(r[2]), "=r"(r[3]) : "r"(addr));
}
__device__ __forceinline__ void mma_bf16(float* d, const uint32_t* a, uint32_t b0, uint32_t b1) {
    asm volatile("mma.sync.aligned.m16n8k16.row.col.f32.bf16.bf16.f32 "
                 "{%0,%1,%2,%3}, {%4,%5,%6,%7}, {%8,%9}, {%0,%1,%2,%3};"
                 : "+f"(d[0]), "+f"(d[1]), "+f"(d[2]), "+f"(d[3])
                 : "r"(a[0]), "r"(a[1]), "r"(a[2]), "r"(a[3]), "r"(b0), "r"(b1));
}
__device__ __forceinline__ float sigmoidf_(float x) { return 1.f / (1.f + expf(-x)); }

// SMEM stage layout (bytes, within dynamic smem)
#define A_HI 0
#define A_LO 8192
#define B_HI 16384
#define B_LO 20480
#define STAGE 24576
#define SMEM_TOTAL (2 * STAGE)   // 49152

// ---------------------------------------------------------------------------
// Prep: split recurrent weights into bf16 hi/lo, rows p-ordered (p = j*4+gate)
// ---------------------------------------------------------------------------
__global__ void prep_weights(const float* __restrict__ w0, const float* __restrict__ w1,
                             const float* __restrict__ w2, const float* __restrict__ w3)
{
    const int p = blockIdx.x;            // 0..4095
    const int j = p >> 2, g = p & 3;
    const float* w = (g == 0) ? w0 : (g == 1) ? w1 : (g == 2) ? w2 : w3;
    const float4 v = *(const float4*)&w[(size_t)j * HH + threadIdx.x * 4];
    const float vv[4] = {v.x, v.y, v.z, v.w};
    size_t base = (size_t)p * HH + threadIdx.x * 4;
#pragma unroll
    for (int i = 0; i < 4; i++) {
        __nv_bfloat16 hi = __float2bfloat16(vv[i]);
        __nv_bfloat16 lo = __float2bfloat16(vv[i] - __bfloat162float(hi));
        g_whi[base + i] = hi;
        g_wlo[base + i] = lo;
    }
}

__global__ void prep_h(const float* __restrict__ hx)
{
    int i = blockIdx.x * blockDim.x + threadIdx.x;   // 0..65535
    float v = hx[i];
    __nv_bfloat16 hi = __float2bfloat16(v);
    g_hhi[0][i] = hi;
    g_hlo[0][i] = __float2bfloat16(v - __bfloat162float(hi));
}

// ---------------------------------------------------------------------------
// Input projection SGEMM (p-ordered columns, bias fused)
// ---------------------------------------------------------------------------
__global__ __launch_bounds__(256) void proj_kernel(
    const float* __restrict__ X,
    const float* __restrict__ wi0, const float* __restrict__ wi1,
    const float* __restrict__ wi2, const float* __restrict__ wi3,
    const float* __restrict__ bi0, const float* __restrict__ bi1,
    const float* __restrict__ bi2, const float* __restrict__ bi3)
{
    __shared__ float A_sh[8][128];
    __shared__ float B_sh[8][128];

    const int tid = threadIdx.x;
    const int n0  = blockIdx.x * 128;      // p-column tile
    const int m0  = blockIdx.y * 128;

    const int lm = tid >> 1;
    const int lk = (tid & 1) * 4;

    const int p_row = n0 + lm;
    const int pg = p_row & 3, pj = p_row >> 2;
    const float* wsel = (pg == 0) ? wi0 : (pg == 1) ? wi1 : (pg == 2) ? wi2 : wi3;

    const float* aptr = X    + (size_t)(m0 + lm) * II + lk;
    const float* bptr = wsel + (size_t)pj * II + lk;

    float4 aReg = *(const float4*)aptr;
    float4 bReg = *(const float4*)bptr;

    const int tx = tid & 15;
    const int ty = tid >> 4;

    float acc[8][8];
#pragma unroll
    for (int i = 0; i < 8; i++)
#pragma unroll
        for (int j = 0; j < 8; j++) acc[i][j] = 0.f;

    for (int kt = 0; kt < II; kt += 8) {
        A_sh[lk + 0][lm] = aReg.x; A_sh[lk + 1][lm] = aReg.y;
        A_sh[lk + 2][lm] = aReg.z; A_sh[lk + 3][lm] = aReg.w;
        B_sh[lk + 0][lm] = bReg.x; B_sh[lk + 1][lm] = bReg.y;
        B_sh[lk + 2][lm] = bReg.z; B_sh[lk + 3][lm] = bReg.w;
        __syncthreads();

        if (kt + 8 < II) {
            aReg = *(const float4*)(aptr + kt + 8);
            bReg = *(const float4*)(bptr + kt + 8);
        }

#pragma unroll
        for (int k = 0; k < 8; k++) {
            float4 a0 = *(const float4*)&A_sh[k][ty * 8];
            float4 a1 = *(const float4*)&A_sh[k][ty * 8 + 4];
            float4 c0 = *(const float4*)&B_sh[k][tx * 8];
            float4 c1 = *(const float4*)&B_sh[k][tx * 8 + 4];
            float av[8] = {a0.x, a0.y, a0.z, a0.w, a1.x, a1.y, a1.z, a1.w};
            float bv[8] = {c0.x, c0.y, c0.z, c0.w, c1.x, c1.y, c1.z, c1.w};
#pragma unroll
            for (int i = 0; i < 8; i++)
#pragma unroll
                for (int j = 0; j < 8; j++) acc[i][j] += av[i] * bv[j];
        }
        __syncthreads();
    }

    float bb[8];
#pragma unroll
    for (int jj = 0; jj < 8; jj++) {
        int p = n0 + tx * 8 + jj;
        int g = p & 3, j = p >> 2;
        const float* bsel = (g == 0) ? bi0 : (g == 1) ? bi1 : (g == 2) ? bi2 : bi3;
        bb[jj] = bsel[j];
    }

#pragma unroll
    for (int i = 0; i < 8; i++) {
        size_t row = (size_t)(m0 + ty * 8 + i) * N4H + n0 + tx * 8;
        float4 v0 = make_float4(acc[i][0] + bb[0], acc[i][1] + bb[1],
                                acc[i][2] + bb[2], acc[i][3] + bb[3]);
        float4 v1 = make_float4(acc[i][4] + bb[4], acc[i][5] + bb[5],
                                acc[i][6] + bb[6], acc[i][7] + bb[7]);
        *(float4*)&g_xp[row]     = v0;
        *(float4*)&g_xp[row + 4] = v1;
    }
}

// ---------------------------------------------------------------------------
// Recurrent step: bf16 split-precision mma.sync GEMM + fused LSTM epilogue.
// CTA c: gate-columns p in [c*32, c*32+32), all 64 batches.
// Warp w: m-subtile (w&3)*16, n-subtile (w>>2)*16 (m16 x n16 per warp).
// K streamed in 16 chunks of 64 (cp.async double-buffered, XOR swizzle).
// 3 split terms (hi*hi + hi*lo + lo*hi) into fp32 accumulators.
// ---------------------------------------------------------------------------
__global__ __launch_bounds__(256) void step_mma_kernel(
    int t, const float* __restrict__ cx_in, float* __restrict__ out)
{
    extern __shared__ char smem[];
    const uint32_t sbase = smem_u32(smem);
    const int tid = threadIdx.x;
    const int cta = blockIdx.x;

    const float* __restrict__ cprev = (t == 0) ? cx_in : g_c;
    const __nv_bfloat16* __restrict__ hhi = g_hhi[t & 1];
    const __nv_bfloat16* __restrict__ hlo = g_hlo[t & 1];
    __nv_bfloat16* __restrict__ nhhi = g_hhi[(t + 1) & 1];
    __nv_bfloat16* __restrict__ nhlo = g_hlo[(t + 1) & 1];
    float* __restrict__ out_t = out + (size_t)t * (BB * HH);
    const float* __restrict__ xp = g_xp + (size_t)t * BB * N4H;

    // per-thread cp.async source/dest mapping
    const int arow = tid >> 3;             // 0..31 (A uses arow and arow+32)
    const int ac16 = tid & 7;
    const uint32_t a_soff0 = (uint32_t)(arow * 128        + ((ac16 ^ (arow & 7)) << 4));
    const uint32_t a_soff1 = (uint32_t)((arow + 32) * 128 + ((ac16 ^ ((arow + 32) & 7)) << 4));
    const size_t   a_goff0 = (size_t)arow * 2048 + ac16 * 16;         // bytes
    const size_t   a_goff1 = (size_t)(arow + 32) * 2048 + ac16 * 16;
    const size_t   b_goff  = (size_t)(cta * NPC + arow) * 2048 + ac16 * 16;
    const uint32_t b_soff  = a_soff0;

    // warp/lane mma mapping
    const int wid  = tid >> 5;
    const int lane = tid & 31;
    const int mrow = (wid & 3) * 16;
    const int ncol = (wid >> 2) * 16;
    const int grp  = lane >> 2;
    const int tig  = lane & 3;
    const int tile = lane >> 3;
    const int lr   = lane & 7;

    const int a_row  = mrow + ((tile & 1) << 3) + lr;
    const uint32_t a_rb = (uint32_t)(a_row * 128);
    const int a_sw = a_row & 7;
    const int a_kt = tile >> 1;

    const int b_row  = ncol + ((tile >> 1) << 3) + lr;
    const uint32_t b_rb = (uint32_t)(b_row * 128);
    const int b_sw = b_row & 7;
    const int b_kt = tile & 1;

    float acc0[4] = {0.f, 0.f, 0.f, 0.f};
    float acc1[4] = {0.f, 0.f, 0.f, 0.f};

    // chunk loader (6 x 16B cp.async per thread)
    auto load_chunk = [&](int kc, int st) {
        const uint32_t sb = sbase + st * STAGE;
        const size_t kb = (size_t)kc * 128;   // byte offset along K
        cp_async16(sb + A_HI + a_soff0, (const char*)hhi + a_goff0 + kb);
        cp_async16(sb + A_HI + a_soff1, (const char*)hhi + a_goff1 + kb);
        cp_async16(sb + A_LO + a_soff0, (const char*)hlo + a_goff0 + kb);
        cp_async16(sb + A_LO + a_soff1, (const char*)hlo + a_goff1 + kb);
        cp_async16(sb + B_HI + b_soff,  (const char*)g_whi + b_goff + kb);
        cp_async16(sb + B_LO + b_soff,  (const char*)g_wlo + b_goff + kb);
        CP_COMMIT();
    };

    load_chunk(0, 0);
    load_chunk(1, 1);

    for (int c = 0; c < NCHUNK; c++) {
        const int st = c & 1;
        if (c < NCHUNK - 1) asm volatile("cp.async.wait_group 1;" ::: "memory");
        else                asm volatile("cp.async.wait_group 0;" ::: "memory");
        __syncthreads();

        const uint32_t sb = sbase + st * STAGE;
#pragma unroll
        for (int ks = 0; ks < 4; ks++) {
            uint32_t a_off = a_rb + ((uint32_t)((ks * 2 + a_kt) ^ a_sw) << 4);
            uint32_t b_off = b_rb + ((uint32_t)((ks * 2 + b_kt) ^ b_sw) << 4);
            uint32_t ah[4], al[4], bh[4], bl[4];
            ldsm4(ah, sb + A_HI + a_off);
            ldsm4(bh, sb + B_HI + b_off);
            ldsm4(al, sb + A_LO + a_off);
            ldsm4(bl, sb + B_LO + b_off);
            mma_bf16(acc0, ah, bh[0], bh[1]);
            mma_bf16(acc1, ah, bh[2], bh[3]);
            mma_bf16(acc0, ah, bl[0], bl[1]);
            mma_bf16(acc1, ah, bl[2], bl[3]);
            mma_bf16(acc0, al, bh[0], bh[1]);
            mma_bf16(acc1, al, bh[2], bh[3]);
        }
        __syncthreads();

        if (c + 2 < NCHUNK) load_chunk(c + 2, st);
    }

    // ---- epilogue: acc -> smem (stride 36), then fused LSTM update ----
    float* ep = (float*)smem;              // reuse stage0 (9216B <= 24576B)
    {
        const int er = mrow + grp;
        const int ec = ncol + 2 * tig;
        ep[er * 36 + ec]           = acc0[0];
        ep[er * 36 + ec + 1]       = acc0[1];
        ep[(er + 8) * 36 + ec]     = acc0[2];
        ep[(er + 8) * 36 + ec + 1] = acc0[3];
        ep[er * 36 + ec + 8]           = acc1[0];
        ep[er * 36 + ec + 9]           = acc1[1];
        ep[(er + 8) * 36 + ec + 8]     = acc1[2];
        ep[(er + 8) * 36 + ec + 9]     = acc1[3];
    }
    __syncthreads();

    if (tid < 64) {
        const int b = tid;
        const float* xpb = xp + (size_t)b * N4H + cta * NPC;
#pragma unroll
        for (int jj = 0; jj < 8; jj++) {
            float4 rv = *(const float4*)&ep[b * 36 + jj * 4];
            float4 xv = *(const float4*)&xpb[jj * 4];
            float gi = rv.x + xv.x;
            float gf = rv.y + xv.y;
            float ga = rv.z + xv.z;
            float go = rv.w + xv.w;
            float ig = sigmoidf_(gi);
            float fg = sigmoidf_(gf);
            float ag = tanhf(ga);
            float og = sigmoidf_(go);
            int j = cta * 8 + jj;
            float cnew = fg * cprev[b * HH + j] + ig * ag;
            float hnew = og * tanhf(cnew);
            g_c[b * HH + j]   = cnew;
            out_t[b * HH + j] = hnew;
            __nv_bfloat16 hi = __float2bfloat16(hnew);
            nhhi[b * HH + j] = hi;
            nhlo[b * HH + j] = __float2bfloat16(hnew - __bfloat162float(hi));
        }
    }
}

// ---------------------------------------------------------------------------
// Finalize: hy = outputs[T-1], cy = g_c
// ---------------------------------------------------------------------------
__global__ void finalize_kernel(float* __restrict__ out)
{
    int i = blockIdx.x * blockDim.x + threadIdx.x;
    const size_t TBH = (size_t)TT * BB * HH;
    out[TBH + i]                   = out[TBH - (size_t)BB * HH + i];
    out[TBH + (size_t)BB * HH + i] = g_c[i];
}

// ---------------------------------------------------------------------------
extern "C" void kernel_launch(void* const* d_in, const int* in_sizes, int n_in,
                              void* d_out, int out_size)
{
    const float* X    = (const float*)d_in[0];
    const float* hx   = (const float*)d_in[1];
    const float* cx   = (const float*)d_in[2];
    const float* w_ii = (const float*)d_in[3];
    const float* w_fi = (const float*)d_in[4];
    const float* w_ai = (const float*)d_in[5];
    const float* w_oi = (const float*)d_in[6];
    const float* w_ih = (const float*)d_in[7];
    const float* w_fh = (const float*)d_in[8];
    const float* w_ah = (const float*)d_in[9];
    const float* w_oh = (const float*)d_in[10];
    const float* b_i  = (const float*)d_in[11];
    const float* b_f  = (const float*)d_in[12];
    const float* b_a  = (const float*)d_in[13];
    const float* b_o  = (const float*)d_in[14];
    float* out = (float*)d_out;

    (void)in_sizes; (void)n_in; (void)out_size;

    cudaFuncSetAttribute(step_mma_kernel, cudaFuncAttributeMaxDynamicSharedMemorySize, SMEM_TOTAL);

    // Prep: weight split (p-ordered) + h0 split
    prep_weights<<<N4H, 256>>>(w_ih, w_fh, w_ah, w_oh);
    prep_h<<<(BB * HH) / 256, 256>>>(hx);

    // Input projections (one big SGEMM, bias fused, p-ordered columns)
    dim3 pg(N4H / 128, MTOT / 128);
    proj_kernel<<<pg, 256>>>(X, w_ii, w_fi, w_ai, w_oi, b_i, b_f, b_a, b_o);

    // Recurrent steps on tensor cores (HMMA via mma.sync)
    for (int t = 0; t < TT; t++) {
        step_mma_kernel<<<NCTA, 256, SMEM_TOTAL>>>(t, cx, out);
    }

    finalize_kernel<<<(BB * HH) / 256, 256>>>(out);
}

// round 4
// speedup vs baseline: 1.4874x; 1.0108x over previous
#include <cuda_runtime.h>
#include <cuda_bf16.h>
#include <math.h>
#include <stdint.h>

// Problem dims
#define TT   512
#define BB   64
#define II   1024
#define HH   1024
#define N4H  4096
#define MTOT (TT*BB)        // 32768

// Step tiling
#define NCTA    128         // persistent CTAs (<= 148 SMs -> co-resident)
#define NPC     32          // gate-output columns (p) per CTA
#define KCHUNK  64          // bf16 K elements per chunk (128B rows)
#define NCHUNK  (HH/KCHUNK) // 16

// ---------------------------------------------------------------------------
// Device scratch (allocation-free)
// ---------------------------------------------------------------------------
__device__ float g_xp[(size_t)MTOT * N4H];        // input projections + bias, p-ordered
__device__ float g_c[BB * HH];                    // cell state (CTA-private columns)
__device__ __nv_bfloat16 g_whi[(size_t)N4H * HH]; // Wh hi, row p = j*4+gate
__device__ __nv_bfloat16 g_wlo[(size_t)N4H * HH]; // Wh lo
__device__ __nv_bfloat16 g_hhi[2][BB * HH];       // h hi, ping-pong by t
__device__ __nv_bfloat16 g_hlo[2][BB * HH];       // h lo
__device__ unsigned g_bar;                        // grid barrier counter

// ---------------------------------------------------------------------------
// Helpers
// ---------------------------------------------------------------------------
__device__ __forceinline__ uint32_t smem_u32(const void* p) {
    uint32_t a;
    asm("{ .reg .u64 t; cvta.to.shared.u64 t, %1; cvt.u32.u64 %0, t; }" : "=r"(a) : "l"(p));
    return a;
}
__device__ __forceinline__ void cp_async16(uint32_t smem_addr, const void* gptr) {
    asm volatile("cp.async.cg.shared.global [%0], [%1], 16;" :: "r"(smem_addr), "l"(gptr));
}
#define CP_COMMIT() asm volatile("cp.async.commit_group;" ::: "memory")

__device__ __forceinline__ void ldsm4(uint32_t* r, uint32_t addr) {
    asm volatile("ldmatrix.sync.aligned.m8n8.x4.shared.b16 {%0,%1,%2,%3}, [%4];"
                 : "=r"(r[0]), "=r"(r[1]), "=r"(r[2]), "=r"(r[3]) : "r"(addr));
}
__device__ __forceinline__ void mma_bf16(float* d, const uint32_t* a, uint32_t b0, uint32_t b1) {
    asm volatile("mma.sync.aligned.m16n8k16.row.col.f32.bf16.bf16.f32 "
                 "{%0,%1,%2,%3}, {%4,%5,%6,%7}, {%8,%9}, {%0,%1,%2,%3};"
                 : "+f"(d[0]), "+f"(d[1]), "+f"(d[2]), "+f"(d[3])
                 : "r"(a[0]), "r"(a[1]), "r"(a[2]), "r"(a[3]), "r"(b0), "r"(b1));
}
__device__ __forceinline__ float sigmoidf_(float x) { return 1.f / (1.f + expf(-x)); }

// SMEM layout (dynamic):
//   W_HI [16 chunks][32 rows][128B swizzled] = 64KB
//   W_LO 64KB
//   A stages: 4 x (A_HI 8KB + A_LO 8KB) = 64KB    (also epilogue scratch)
#define W_HI_OFF 0
#define W_LO_OFF 65536
#define A_BASE   131072
#define A_ST(s)  (A_BASE + (s) * 16384)
#define SMEM_TOTAL 196608   // 192KB <= 227KB cap

// ---------------------------------------------------------------------------
// Prep kernels
// ---------------------------------------------------------------------------
__global__ void prep_weights(const float* __restrict__ w0, const float* __restrict__ w1,
                             const float* __restrict__ w2, const float* __restrict__ w3)
{
    const int p = blockIdx.x;            // 0..4095
    const int j = p >> 2, g = p & 3;
    const float* w = (g == 0) ? w0 : (g == 1) ? w1 : (g == 2) ? w2 : w3;
    const float4 v = *(const float4*)&w[(size_t)j * HH + threadIdx.x * 4];
    const float vv[4] = {v.x, v.y, v.z, v.w};
    size_t base = (size_t)p * HH + threadIdx.x * 4;
#pragma unroll
    for (int i = 0; i < 4; i++) {
        __nv_bfloat16 hi = __float2bfloat16(vv[i]);
        __nv_bfloat16 lo = __float2bfloat16(vv[i] - __bfloat162float(hi));
        g_whi[base + i] = hi;
        g_wlo[base + i] = lo;
    }
}

__global__ void prep_h(const float* __restrict__ hx)
{
    int i = blockIdx.x * blockDim.x + threadIdx.x;   // 0..65535
    float v = hx[i];
    __nv_bfloat16 hi = __float2bfloat16(v);
    g_hhi[0][i] = hi;
    g_hlo[0][i] = __float2bfloat16(v - __bfloat162float(hi));
    if (i == 0) g_bar = 0u;                          // reset grid barrier each replay
}

// ---------------------------------------------------------------------------
// Input projection SGEMM (p-ordered columns, bias fused) — unchanged
// ---------------------------------------------------------------------------
__global__ __launch_bounds__(256) void proj_kernel(
    const float* __restrict__ X,
    const float* __restrict__ wi0, const float* __restrict__ wi1,
    const float* __restrict__ wi2, const float* __restrict__ wi3,
    const float* __restrict__ bi0, const float* __restrict__ bi1,
    const float* __restrict__ bi2, const float* __restrict__ bi3)
{
    __shared__ float A_sh[8][128];
    __shared__ float B_sh[8][128];

    const int tid = threadIdx.x;
    const int n0  = blockIdx.x * 128;
    const int m0  = blockIdx.y * 128;

    const int lm = tid >> 1;
    const int lk = (tid & 1) * 4;

    const int p_row = n0 + lm;
    const int pg = p_row & 3, pj = p_row >> 2;
    const float* wsel = (pg == 0) ? wi0 : (pg == 1) ? wi1 : (pg == 2) ? wi2 : wi3;

    const float* aptr = X    + (size_t)(m0 + lm) * II + lk;
    const float* bptr = wsel + (size_t)pj * II + lk;

    float4 aReg = *(const float4*)aptr;
    float4 bReg = *(const float4*)bptr;

    const int tx = tid & 15;
    const int ty = tid >> 4;

    float acc[8][8];
#pragma unroll
    for (int i = 0; i < 8; i++)
#pragma unroll
        for (int j = 0; j < 8; j++) acc[i][j] = 0.f;

    for (int kt = 0; kt < II; kt += 8) {
        A_sh[lk + 0][lm] = aReg.x; A_sh[lk + 1][lm] = aReg.y;
        A_sh[lk + 2][lm] = aReg.z; A_sh[lk + 3][lm] = aReg.w;
        B_sh[lk + 0][lm] = bReg.x; B_sh[lk + 1][lm] = bReg.y;
        B_sh[lk + 2][lm] = bReg.z; B_sh[lk + 3][lm] = bReg.w;
        __syncthreads();

        if (kt + 8 < II) {
            aReg = *(const float4*)(aptr + kt + 8);
            bReg = *(const float4*)(bptr + kt + 8);
        }

#pragma unroll
        for (int k = 0; k < 8; k++) {
            float4 a0 = *(const float4*)&A_sh[k][ty * 8];
            float4 a1 = *(const float4*)&A_sh[k][ty * 8 + 4];
            float4 c0 = *(const float4*)&B_sh[k][tx * 8];
            float4 c1 = *(const float4*)&B_sh[k][tx * 8 + 4];
            float av[8] = {a0.x, a0.y, a0.z, a0.w, a1.x, a1.y, a1.z, a1.w};
            float bv[8] = {c0.x, c0.y, c0.z, c0.w, c1.x, c1.y, c1.z, c1.w};
#pragma unroll
            for (int i = 0; i < 8; i++)
#pragma unroll
                for (int j = 0; j < 8; j++) acc[i][j] += av[i] * bv[j];
        }
        __syncthreads();
    }

    float bb[8];
#pragma unroll
    for (int jj = 0; jj < 8; jj++) {
        int p = n0 + tx * 8 + jj;
        int g = p & 3, j = p >> 2;
        const float* bsel = (g == 0) ? bi0 : (g == 1) ? bi1 : (g == 2) ? bi2 : bi3;
        bb[jj] = bsel[j];
    }

#pragma unroll
    for (int i = 0; i < 8; i++) {
        size_t row = (size_t)(m0 + ty * 8 + i) * N4H + n0 + tx * 8;
        float4 v0 = make_float4(acc[i][0] + bb[0], acc[i][1] + bb[1],
                                acc[i][2] + bb[2], acc[i][3] + bb[3]);
        float4 v1 = make_float4(acc[i][4] + bb[4], acc[i][5] + bb[5],
                                acc[i][6] + bb[6], acc[i][7] + bb[7]);
        *(float4*)&g_xp[row]     = v0;
        *(float4*)&g_xp[row + 4] = v1;
    }
}

// ---------------------------------------------------------------------------
// Persistent recurrent kernel: all 512 steps in one launch.
// CTA c: gate-columns p in [c*32, c*32+32), all 64 batches.
// Weights (hi+lo, this CTA's 32 rows, full K) resident in SMEM (128KB).
// Per step: h streamed in 16 chunks (4-stage cp.async pipeline), 3-term
// split-precision HMMA, fused LSTM epilogue, then grid barrier.
// ---------------------------------------------------------------------------
__global__ __launch_bounds__(256) void lstm_persist_kernel(
    const float* __restrict__ cx_in, float* __restrict__ out)
{
    extern __shared__ char smem[];
    const uint32_t sbase = smem_u32(smem);
    const int tid = threadIdx.x;
    const int cta = blockIdx.x;

    // ---- one-time: load this CTA's weight slice into SMEM (swizzled, chunk-major) ----
    {
#pragma unroll
        for (int i = 0; i < 16; i++) {
            int u = tid + i * 256;            // 0..4095 16B-units
            int kc  = u >> 8;
            int rem = u & 255;
            int row = rem >> 3;
            int c16 = u & 7;
            uint32_t soff = (uint32_t)(kc * 4096 + row * 128 + ((c16 ^ (row & 7)) << 4));
            size_t   goff = (size_t)(cta * NPC + row) * 2048 + (size_t)kc * 128 + c16 * 16;
            cp_async16(sbase + W_HI_OFF + soff, (const char*)g_whi + goff);
            cp_async16(sbase + W_LO_OFF + soff, (const char*)g_wlo + goff);
        }
        CP_COMMIT();
        asm volatile("cp.async.wait_group 0;" ::: "memory");
        __syncthreads();
    }

    // ---- per-thread A-load mapping (4 cp.async / chunk) ----
    const int arow = tid >> 3;             // 0..31 (A rows arow, arow+32)
    const int ac16 = tid & 7;
    const uint32_t a_soff0 = (uint32_t)(arow * 128        + ((ac16 ^ (arow & 7)) << 4));
    const uint32_t a_soff1 = (uint32_t)((arow + 32) * 128 + ((ac16 ^ ((arow + 32) & 7)) << 4));
    const size_t   a_goff0 = (size_t)arow * 2048 + ac16 * 16;
    const size_t   a_goff1 = (size_t)(arow + 32) * 2048 + ac16 * 16;

    // ---- warp/lane mma mapping ----
    const int wid  = tid >> 5;
    const int lane = tid & 31;
    const int mrow = (wid & 3) * 16;
    const int ncol = (wid >> 2) * 16;
    const int grp  = lane >> 2;
    const int tig  = lane & 3;
    const int tile = lane >> 3;
    const int lr   = lane & 7;

    const int a_row  = mrow + ((tile & 1) << 3) + lr;
    const uint32_t a_rb = (uint32_t)(a_row * 128);
    const int a_sw = a_row & 7;
    const int a_kt = tile >> 1;

    const int b_row  = ncol + ((tile >> 1) << 3) + lr;
    const uint32_t b_rb = (uint32_t)(b_row * 128);
    const int b_sw = b_row & 7;
    const int b_kt = tile & 1;

    const int ep_r = mrow + grp;
    const int ep_c = ncol + 2 * tig;
    float* ep = (float*)(smem + A_BASE);   // epilogue scratch: 64*36*4 = 9216B

    for (int t = 0; t < TT; t++) {
        const float* __restrict__ cprev = (t == 0) ? cx_in : g_c;
        const __nv_bfloat16* __restrict__ hhi = g_hhi[t & 1];
        const __nv_bfloat16* __restrict__ hlo = g_hlo[t & 1];
        __nv_bfloat16* __restrict__ nhhi = g_hhi[(t + 1) & 1];
        __nv_bfloat16* __restrict__ nhlo = g_hlo[(t + 1) & 1];
        float* __restrict__ out_t = out + (size_t)t * (BB * HH);
        const float* __restrict__ xp = g_xp + (size_t)t * BB * N4H;

        // A chunk loader
        auto load_chunk = [&](int kc, int st) {
            const uint32_t sb = sbase + A_ST(st);
            const size_t kb = (size_t)kc * 128;
            cp_async16(sb + a_soff0,        (const char*)hhi + a_goff0 + kb);
            cp_async16(sb + a_soff1,        (const char*)hhi + a_goff1 + kb);
            cp_async16(sb + 8192 + a_soff0, (const char*)hlo + a_goff0 + kb);
            cp_async16(sb + 8192 + a_soff1, (const char*)hlo + a_goff1 + kb);
            CP_COMMIT();
        };

        load_chunk(0, 0);
        load_chunk(1, 1);
        load_chunk(2, 2);

        float acc0[4] = {0.f, 0.f, 0.f, 0.f};
        float acc1[4] = {0.f, 0.f, 0.f, 0.f};

        for (int c = 0; c < NCHUNK; c++) {
            if (c < NCHUNK - 2)      asm volatile("cp.async.wait_group 2;" ::: "memory");
            else if (c == NCHUNK - 2) asm volatile("cp.async.wait_group 1;" ::: "memory");
            else                      asm volatile("cp.async.wait_group 0;" ::: "memory");
            __syncthreads();

            const uint32_t asb = sbase + A_ST(c & 3);
            const uint32_t wb  = (uint32_t)(c * 4096);
#pragma unroll
            for (int ks = 0; ks < 4; ks++) {
                uint32_t a_off = a_rb + ((uint32_t)((ks * 2 + a_kt) ^ a_sw) << 4);
                uint32_t b_off = wb + b_rb + ((uint32_t)((ks * 2 + b_kt) ^ b_sw) << 4);
                uint32_t ah[4], al[4], bh[4], bl[4];
                ldsm4(ah, asb + a_off);
                ldsm4(bh, sbase + W_HI_OFF + b_off);
                ldsm4(al, asb + 8192 + a_off);
                ldsm4(bl, sbase + W_LO_OFF + b_off);
                mma_bf16(acc0, ah, bh[0], bh[1]);
                mma_bf16(acc1, ah, bh[2], bh[3]);
                mma_bf16(acc0, ah, bl[0], bl[1]);
                mma_bf16(acc1, ah, bl[2], bl[3]);
                mma_bf16(acc0, al, bh[0], bh[1]);
                mma_bf16(acc1, al, bh[2], bh[3]);
            }

            if (c + 3 < NCHUNK) load_chunk(c + 3, (c + 3) & 3);
        }

        // ---- epilogue ----
        __syncthreads();                    // all ldsm done before scratch reuse
        ep[ep_r * 36 + ep_c]           = acc0[0];
        ep[ep_r * 36 + ep_c + 1]       = acc0[1];
        ep[(ep_r + 8) * 36 + ep_c]     = acc0[2];
        ep[(ep_r + 8) * 36 + ep_c + 1] = acc0[3];
        ep[ep_r * 36 + ep_c + 8]       = acc1[0];
        ep[ep_r * 36 + ep_c + 9]       = acc1[1];
        ep[(ep_r + 8) * 36 + ep_c + 8] = acc1[2];
        ep[(ep_r + 8) * 36 + ep_c + 9] = acc1[3];
        __syncthreads();

        if (tid < 64) {
            const int b = tid;
            const float* xpb = xp + (size_t)b * N4H + cta * NPC;
#pragma unroll
            for (int jj = 0; jj < 8; jj++) {
                float4 rv = *(const float4*)&ep[b * 36 + jj * 4];
                float4 xv = *(const float4*)&xpb[jj * 4];
                float gi = rv.x + xv.x;
                float gf = rv.y + xv.y;
                float ga = rv.z + xv.z;
                float go = rv.w + xv.w;
                float ig = sigmoidf_(gi);
                float fg = sigmoidf_(gf);
                float ag = tanhf(ga);
                float og = sigmoidf_(go);
                int j = cta * 8 + jj;
                float cnew = fg * cprev[b * HH + j] + ig * ag;
                float hnew = og * tanhf(cnew);
                g_c[b * HH + j]   = cnew;
                out_t[b * HH + j] = hnew;
                __nv_bfloat16 hi = __float2bfloat16(hnew);
                nhhi[b * HH + j] = hi;
                nhlo[b * HH + j] = __float2bfloat16(hnew - __bfloat162float(hi));
            }
        }

        // ---- grid barrier (skip after last step) ----
        if (t + 1 < TT) {
            __threadfence();                // release h writes
            __syncthreads();                // CTA done with epilogue + scratch
            if (tid == 0) {
                atomicAdd(&g_bar, 1u);
                const unsigned target = (unsigned)NCTA * (unsigned)(t + 1);
                unsigned v;
                do {
                    asm volatile("ld.global.acquire.gpu.u32 %0, [%1];"
                                 : "=r"(v) : "l"(&g_bar));
                    if (v < target) __nanosleep(32);
                } while (v < target);
            }
            __syncthreads();
        }
    }
}

// ---------------------------------------------------------------------------
// Finalize: hy = outputs[T-1], cy = g_c
// ---------------------------------------------------------------------------
__global__ void finalize_kernel(float* __restrict__ out)
{
    int i = blockIdx.x * blockDim.x + threadIdx.x;
    const size_t TBH = (size_t)TT * BB * HH;
    out[TBH + i]                   = out[TBH - (size_t)BB * HH + i];
    out[TBH + (size_t)BB * HH + i] = g_c[i];
}

// ---------------------------------------------------------------------------
extern "C" void kernel_launch(void* const* d_in, const int* in_sizes, int n_in,
                              void* d_out, int out_size)
{
    const float* X    = (const float*)d_in[0];
    const float* hx   = (const float*)d_in[1];
    const float* cx   = (const float*)d_in[2];
    const float* w_ii = (const float*)d_in[3];
    const float* w_fi = (const float*)d_in[4];
    const float* w_ai = (const float*)d_in[5];
    const float* w_oi = (const float*)d_in[6];
    const float* w_ih = (const float*)d_in[7];
    const float* w_fh = (const float*)d_in[8];
    const float* w_ah = (const float*)d_in[9];
    const float* w_oh = (const float*)d_in[10];
    const float* b_i  = (const float*)d_in[11];
    const float* b_f  = (const float*)d_in[12];
    const float* b_a  = (const float*)d_in[13];
    const float* b_o  = (const float*)d_in[14];
    float* out = (float*)d_out;

    (void)in_sizes; (void)n_in; (void)out_size;

    cudaFuncSetAttribute(lstm_persist_kernel,
                         cudaFuncAttributeMaxDynamicSharedMemorySize, SMEM_TOTAL);

    // Prep: weight split (p-ordered) + h0 split + barrier reset
    prep_weights<<<N4H, 256>>>(w_ih, w_fh, w_ah, w_oh);
    prep_h<<<(BB * HH) / 256, 256>>>(hx);

    // Input projections (one big SGEMM, bias fused, p-ordered columns)
    dim3 pg(N4H / 128, MTOT / 128);
    proj_kernel<<<pg, 256>>>(X, w_ii, w_fi, w_ai, w_oi, b_i, b_f, b_a, b_o);

    // All 512 recurrent steps in ONE persistent launch
    lstm_persist_kernel<<<NCTA, 256, SMEM_TOTAL>>>(cx, out);

    finalize_kernel<<<(BB * HH) / 256, 256>>>(out);
}

// round 5
// speedup vs baseline: 2.8517x; 1.9172x over previous
#include <cuda_runtime.h>
#include <cuda_bf16.h>
#include <math.h>
#include <stdint.h>

// Problem dims
#define TT   512
#define BB   64
#define II   1024
#define HH   1024
#define N4H  4096
#define MTOT (TT*BB)        // 32768

// Step tiling
#define NCTA    128
#define NPC     32          // gate-output columns (p) per CTA
#define KCHUNK  64
#define NCHUNK  (HH/KCHUNK) // 16

// ---------------------------------------------------------------------------
// Device scratch (allocation-free)
// ---------------------------------------------------------------------------
__device__ float g_xp[(size_t)MTOT * N4H];         // input projections + bias, p-ordered
__device__ float g_c[BB * HH];                     // cell state
__device__ __nv_bfloat16 g_whi[(size_t)N4H * HH];  // Wh hi (p-ordered rows)
__device__ __nv_bfloat16 g_wlo[(size_t)N4H * HH];  // Wh lo
__device__ __nv_bfloat16 g_hhi[2][BB * HH];        // h hi ping-pong
__device__ __nv_bfloat16 g_hlo[2][BB * HH];        // h lo
__device__ __nv_bfloat16 g_xhi[(size_t)MTOT * II]; // X hi
__device__ __nv_bfloat16 g_xlo[(size_t)MTOT * II]; // X lo
__device__ __nv_bfloat16 g_wihi[(size_t)N4H * II]; // Wi hi (p-ordered rows)
__device__ __nv_bfloat16 g_wilo[(size_t)N4H * II]; // Wi lo
__device__ float g_bp[N4H];                        // bias, p-ordered
__device__ unsigned g_bar;                         // grid barrier counter

// ---------------------------------------------------------------------------
// Helpers
// ---------------------------------------------------------------------------
__device__ __forceinline__ uint32_t smem_u32(const void* p) {
    uint32_t a;
    asm("{ .reg .u64 t; cvta.to.shared.u64 t, %1; cvt.u32.u64 %0, t; }" : "=r"(a) : "l"(p));
    return a;
}
__device__ __forceinline__ void cp_async16(uint32_t smem_addr, const void* gptr) {
    asm volatile("cp.async.cg.shared.global [%0], [%1], 16;" :: "r"(smem_addr), "l"(gptr));
}
#define CP_COMMIT() asm volatile("cp.async.commit_group;" ::: "memory")

__device__ __forceinline__ void ldsm4(uint32_t* r, uint32_t addr) {
    asm volatile("ldmatrix.sync.aligned.m8n8.x4.shared.b16 {%0,%1,%2,%3}, [%4];"
                 : "=r"(r[0]), "=r"(r[1]), "=r"(r[2]), "=r"(r[3]) : "r"(addr));
}
__device__ __forceinline__ void ldsm2(uint32_t* r, uint32_t addr) {
    asm volatile("ldmatrix.sync.aligned.m8n8.x2.shared.b16 {%0,%1}, [%2];"
                 : "=r"(r[0]), "=r"(r[1]) : "r"(addr));
}
__device__ __forceinline__ void mma_bf16(float* d, const uint32_t* a, uint32_t b0, uint32_t b1) {
    asm volatile("mma.sync.aligned.m16n8k16.row.col.f32.bf16.bf16.f32 "
                 "{%0,%1,%2,%3}, {%4,%5,%6,%7}, {%8,%9}, {%0,%1,%2,%3};"
                 : "+f"(d[0]), "+f"(d[1]), "+f"(d[2]), "+f"(d[3])
                 : "r"(a[0]), "r"(a[1]), "r"(a[2]), "r"(a[3]), "r"(b0), "r"(b1));
}
__device__ __forceinline__ float sigmoidf_(float x) { return 1.f / (1.f + expf(-x)); }
#define SWZ(row, c16) ((uint32_t)((row) * 128 + (((c16) ^ ((row) & 7)) << 4)))

// ---------------------------------------------------------------------------
// Prep kernels
// ---------------------------------------------------------------------------
__global__ void prep_wh(const float* __restrict__ w0, const float* __restrict__ w1,
                        const float* __restrict__ w2, const float* __restrict__ w3)
{
    const int p = blockIdx.x;
    const int j = p >> 2, g = p & 3;
    const float* w = (g == 0) ? w0 : (g == 1) ? w1 : (g == 2) ? w2 : w3;
    const float4 v = *(const float4*)&w[(size_t)j * HH + threadIdx.x * 4];
    const float vv[4] = {v.x, v.y, v.z, v.w};
    size_t base = (size_t)p * HH + threadIdx.x * 4;
#pragma unroll
    for (int i = 0; i < 4; i++) {
        __nv_bfloat16 hi = __float2bfloat16(vv[i]);
        g_whi[base + i] = hi;
        g_wlo[base + i] = __float2bfloat16(vv[i] - __bfloat162float(hi));
    }
}

__global__ void prep_wi(const float* __restrict__ w0, const float* __restrict__ w1,
                        const float* __restrict__ w2, const float* __restrict__ w3)
{
    const int p = blockIdx.x;
    const int j = p >> 2, g = p & 3;
    const float* w = (g == 0) ? w0 : (g == 1) ? w1 : (g == 2) ? w2 : w3;
    const float4 v = *(const float4*)&w[(size_t)j * II + threadIdx.x * 4];
    const float vv[4] = {v.x, v.y, v.z, v.w};
    size_t base = (size_t)p * II + threadIdx.x * 4;
#pragma unroll
    for (int i = 0; i < 4; i++) {
        __nv_bfloat16 hi = __float2bfloat16(vv[i]);
        g_wihi[base + i] = hi;
        g_wilo[base + i] = __float2bfloat16(vv[i] - __bfloat162float(hi));
    }
}

__global__ void prep_bias(const float* __restrict__ b0, const float* __restrict__ b1,
                          const float* __restrict__ b2, const float* __restrict__ b3)
{
    int p = blockIdx.x * blockDim.x + threadIdx.x;   // 0..4095
    int j = p >> 2, g = p & 3;
    const float* b = (g == 0) ? b0 : (g == 1) ? b1 : (g == 2) ? b2 : b3;
    g_bp[p] = b[j];
}

__global__ void prep_x(const float* __restrict__ X)
{
    size_t i = (size_t)blockIdx.x * blockDim.x + threadIdx.x;   // 0..8388607
    float4 v = *(const float4*)&X[i * 4];
    const float vv[4] = {v.x, v.y, v.z, v.w};
#pragma unroll
    for (int k = 0; k < 4; k++) {
        __nv_bfloat16 hi = __float2bfloat16(vv[k]);
        g_xhi[i * 4 + k] = hi;
        g_xlo[i * 4 + k] = __float2bfloat16(vv[k] - __bfloat162float(hi));
    }
}

__global__ void prep_h(const float* __restrict__ hx)
{
    int i = blockIdx.x * blockDim.x + threadIdx.x;
    float v = hx[i];
    __nv_bfloat16 hi = __float2bfloat16(v);
    g_hhi[0][i] = hi;
    g_hlo[0][i] = __float2bfloat16(v - __bfloat162float(hi));
    if (i == 0) g_bar = 0u;
}

// ---------------------------------------------------------------------------
// Input projection on tensor cores: g_xp[m][p] = bias[p] + X[m]·Wi[p]
// 3-term split-precision bf16 HMMA. CTA tile 128m x 128n, 16 warps m32n32.
// ---------------------------------------------------------------------------
#define PA_HI 0
#define PA_LO 16384
#define PB_HI 32768
#define PB_LO 49152
#define PSTAGE 65536
#define PSMEM (2 * PSTAGE)   // 131072

__global__ __launch_bounds__(512) void proj_hmma_kernel()
{
    extern __shared__ char smem[];
    const uint32_t sbase = smem_u32(smem);
    const int tid = threadIdx.x;
    const int m0 = blockIdx.y * 128;
    const int n0 = blockIdx.x * 128;

    // chunk loader: 8 cp.async16 per thread
    auto load_chunk = [&](int kc, int st) {
        const uint32_t sb = sbase + st * PSTAGE;
#pragma unroll
        for (int i = 0; i < 2; i++) {
            int u = tid + i * 512;          // 0..1023
            int row = u >> 3, c16 = u & 7;
            uint32_t soff = SWZ(row, c16);
            size_t gx = ((size_t)(m0 + row) * II + kc * KCHUNK + c16 * 8) * 2;
            size_t gw = ((size_t)(n0 + row) * II + kc * KCHUNK + c16 * 8) * 2;
            cp_async16(sb + PA_HI + soff, (const char*)g_xhi + gx);
            cp_async16(sb + PA_LO + soff, (const char*)g_xlo + gx);
            cp_async16(sb + PB_HI + soff, (const char*)g_wihi + gw);
            cp_async16(sb + PB_LO + soff, (const char*)g_wilo + gw);
        }
        CP_COMMIT();
    };

    // warp/lane mapping
    const int wid  = tid >> 5;
    const int lane = tid & 31;
    const int mrow = (wid & 3) * 32;
    const int ncol = (wid >> 2) * 32;
    const int grp  = lane >> 2;
    const int tig  = lane & 3;
    const int tile = lane >> 3;
    const int lr   = lane & 7;

    int a_r[2], b_r[2];
    a_r[0] = mrow + (tile & 1) * 8 + lr;
    a_r[1] = a_r[0] + 16;
    b_r[0] = ncol + (tile >> 1) * 8 + lr;
    b_r[1] = b_r[0] + 16;
    const int a_kt = tile >> 1;
    const int b_kt = tile & 1;

    float acc[2][4][4];
#pragma unroll
    for (int mt = 0; mt < 2; mt++)
#pragma unroll
        for (int n = 0; n < 4; n++)
#pragma unroll
            for (int i = 0; i < 4; i++) acc[mt][n][i] = 0.f;

    load_chunk(0, 0);
    load_chunk(1, 1);

    for (int kc = 0; kc < NCHUNK; kc++) {
        if (kc < NCHUNK - 1) asm volatile("cp.async.wait_group 1;" ::: "memory");
        else                 asm volatile("cp.async.wait_group 0;" ::: "memory");
        __syncthreads();

        const uint32_t sb = sbase + (kc & 1) * PSTAGE;
#pragma unroll
        for (int ks = 0; ks < 4; ks++) {
            uint32_t ah[2][4], al[2][4], bh[2][4], bl[2][4];
#pragma unroll
            for (int mt = 0; mt < 2; mt++) {
                uint32_t ao = a_r[mt] * 128 + ((uint32_t)((ks * 2 + a_kt) ^ (a_r[mt] & 7)) << 4);
                ldsm4(ah[mt], sb + PA_HI + ao);
                ldsm4(al[mt], sb + PA_LO + ao);
            }
#pragma unroll
            for (int nt = 0; nt < 2; nt++) {
                uint32_t bo = b_r[nt] * 128 + ((uint32_t)((ks * 2 + b_kt) ^ (b_r[nt] & 7)) << 4);
                ldsm4(bh[nt], sb + PB_HI + bo);
                ldsm4(bl[nt], sb + PB_LO + bo);
            }
#pragma unroll
            for (int mt = 0; mt < 2; mt++)
#pragma unroll
                for (int nt = 0; nt < 2; nt++) {
                    mma_bf16(acc[mt][2 * nt],     ah[mt], bh[nt][0], bh[nt][1]);
                    mma_bf16(acc[mt][2 * nt + 1], ah[mt], bh[nt][2], bh[nt][3]);
                    mma_bf16(acc[mt][2 * nt],     ah[mt], bl[nt][0], bl[nt][1]);
                    mma_bf16(acc[mt][2 * nt + 1], ah[mt], bl[nt][2], bl[nt][3]);
                    mma_bf16(acc[mt][2 * nt],     al[mt], bh[nt][0], bh[nt][1]);
                    mma_bf16(acc[mt][2 * nt + 1], al[mt], bh[nt][2], bh[nt][3]);
                }
        }
        __syncthreads();
        if (kc + 2 < NCHUNK) load_chunk(kc + 2, kc & 1);
    }

    // epilogue: bias + store fp32
#pragma unroll
    for (int mt = 0; mt < 2; mt++) {
        const int r0 = m0 + mrow + mt * 16 + grp;
#pragma unroll
        for (int n8 = 0; n8 < 4; n8++) {
            const int col = n0 + ncol + n8 * 8 + 2 * tig;
            const float b0 = g_bp[col], b1 = g_bp[col + 1];
            float2 v0 = make_float2(acc[mt][n8][0] + b0, acc[mt][n8][1] + b1);
            float2 v1 = make_float2(acc[mt][n8][2] + b0, acc[mt][n8][3] + b1);
            *(float2*)&g_xp[(size_t)r0 * N4H + col]       = v0;
            *(float2*)&g_xp[(size_t)(r0 + 8) * N4H + col] = v1;
        }
    }
}

// ---------------------------------------------------------------------------
// Persistent recurrent kernel: 512 threads / 16 warps, warp tile m16n8,
// dual accumulator chains, weights SMEM-resident, grid barrier per step.
// ---------------------------------------------------------------------------
#define W_HI_OFF 0
#define W_LO_OFF 65536
#define A_BASE   131072
#define A_ST(s)  (A_BASE + (s) * 16384)
#define SMEM_TOTAL 196608

__global__ __launch_bounds__(512) void lstm_persist_kernel(
    const float* __restrict__ cx_in, float* __restrict__ out)
{
    extern __shared__ char smem[];
    const uint32_t sbase = smem_u32(smem);
    const int tid = threadIdx.x;
    const int cta = blockIdx.x;

    // one-time: weights (hi+lo) into SMEM, chunk-major, swizzled
    {
#pragma unroll
        for (int i = 0; i < 8; i++) {
            int u = tid + i * 512;            // 0..4095
            int kc  = u >> 8;
            int row = (u & 255) >> 3;
            int c16 = u & 7;
            uint32_t soff = (uint32_t)(kc * 4096) + SWZ(row, c16);
            size_t   goff = (size_t)(cta * NPC + row) * (HH * 2) + (size_t)kc * 128 + c16 * 16;
            cp_async16(sbase + W_HI_OFF + soff, (const char*)g_whi + goff);
            cp_async16(sbase + W_LO_OFF + soff, (const char*)g_wlo + goff);
        }
        CP_COMMIT();
        asm volatile("cp.async.wait_group 0;" ::: "memory");
        __syncthreads();
    }

    // A-load mapping: 1 hi + 1 lo cp.async per thread per chunk
    const int arow = tid >> 3;             // 0..63
    const int ac16 = tid & 7;
    const uint32_t a_soff = SWZ(arow, ac16);
    const size_t   a_goff = (size_t)arow * (HH * 2) + ac16 * 16;

    // warp/lane mma mapping (warp tile m16n8)
    const int wid  = tid >> 5;
    const int lane = tid & 31;
    const int mrow = (wid & 3) * 16;
    const int ncol = (wid >> 2) * 8;
    const int grp  = lane >> 2;
    const int tig  = lane & 3;
    const int tile = lane >> 3;
    const int lr   = lane & 7;

    const int a_row = mrow + (tile & 1) * 8 + lr;
    const int a_kt  = tile >> 1;
    const int b_row = ncol + lr;
    const int b_kt  = tile & 1;              // lanes 16-31 mirror 0-15 (ignored by x2)

    const int ep_r = mrow + grp;
    const int ep_c = ncol + 2 * tig;
    float* ep = (float*)(smem + A_BASE);     // 64 x 36 fp32 scratch (9216B, stage0 region)

    for (int t = 0; t < TT; t++) {
        const float* __restrict__ cprev = (t == 0) ? cx_in : g_c;
        const __nv_bfloat16* __restrict__ hhi = g_hhi[t & 1];
        const __nv_bfloat16* __restrict__ hlo = g_hlo[t & 1];
        __nv_bfloat16* __restrict__ nhhi = g_hhi[(t + 1) & 1];
        __nv_bfloat16* __restrict__ nhlo = g_hlo[(t + 1) & 1];
        float* __restrict__ out_t = out + (size_t)t * (BB * HH);
        const float* __restrict__ xp = g_xp + (size_t)t * BB * N4H;

        auto load_chunk = [&](int kc, int st) {
            const uint32_t sb = sbase + A_ST(st);
            const size_t kb = (size_t)kc * 128;
            cp_async16(sb + a_soff,        (const char*)hhi + a_goff + kb);
            cp_async16(sb + 8192 + a_soff, (const char*)hlo + a_goff + kb);
            CP_COMMIT();
        };

        load_chunk(0, 0);
        load_chunk(1, 1);
        load_chunk(2, 2);

        float acc_h[4] = {0.f, 0.f, 0.f, 0.f};
        float acc_m[4] = {0.f, 0.f, 0.f, 0.f};

        for (int c = 0; c < NCHUNK; c++) {
            if (c < NCHUNK - 2)       asm volatile("cp.async.wait_group 2;" ::: "memory");
            else if (c == NCHUNK - 2) asm volatile("cp.async.wait_group 1;" ::: "memory");
            else                      asm volatile("cp.async.wait_group 0;" ::: "memory");
            __syncthreads();

            const uint32_t asb = sbase + A_ST(c & 3);
            const uint32_t wb  = (uint32_t)(c * 4096);
#pragma unroll
            for (int ks = 0; ks < 4; ks++) {
                uint32_t ao = a_row * 128 + ((uint32_t)((ks * 2 + a_kt) ^ (a_row & 7)) << 4);
                uint32_t bo = wb + b_row * 128 + ((uint32_t)((ks * 2 + b_kt) ^ (b_row & 7)) << 4);
                uint32_t ah[4], al[4], bh[2], bl[2];
                ldsm4(ah, asb + ao);
                ldsm2(bh, sbase + W_HI_OFF + bo);
                ldsm4(al, asb + 8192 + ao);
                ldsm2(bl, sbase + W_LO_OFF + bo);
                mma_bf16(acc_h, ah, bh[0], bh[1]);   // chain 1
                mma_bf16(acc_m, ah, bl[0], bl[1]);   // chain 2
                mma_bf16(acc_m, al, bh[0], bh[1]);
            }

            if (c + 3 < NCHUNK) load_chunk(c + 3, (c + 3) & 3);
        }

        // epilogue: reduce chains, stage via smem, fused LSTM update (512 thr)
        ep[ep_r * 36 + ep_c]           = acc_h[0] + acc_m[0];
        ep[ep_r * 36 + ep_c + 1]       = acc_h[1] + acc_m[1];
        ep[(ep_r + 8) * 36 + ep_c]     = acc_h[2] + acc_m[2];
        ep[(ep_r + 8) * 36 + ep_c + 1] = acc_h[3] + acc_m[3];
        __syncthreads();

        {
            const int b  = tid >> 3;
            const int jj = tid & 7;
            float4 rv = *(const float4*)&ep[b * 36 + jj * 4];
            float4 xv = *(const float4*)&xp[(size_t)b * N4H + cta * NPC + jj * 4];
            float gi = rv.x + xv.x;
            float gf = rv.y + xv.y;
            float ga = rv.z + xv.z;
            float go = rv.w + xv.w;
            float ig = sigmoidf_(gi);
            float fg = sigmoidf_(gf);
            float ag = tanhf(ga);
            float og = sigmoidf_(go);
            int j = cta * 8 + jj;
            float cnew = fg * cprev[b * HH + j] + ig * ag;
            float hnew = og * tanhf(cnew);
            g_c[b * HH + j]   = cnew;
            out_t[b * HH + j] = hnew;
            __nv_bfloat16 hi = __float2bfloat16(hnew);
            nhhi[b * HH + j] = hi;
            nhlo[b * HH + j] = __float2bfloat16(hnew - __bfloat162float(hi));
        }

        // grid barrier (CG-style: bar, tid0 fence+arrive, tid0 spin, bar)
        if (t + 1 < TT) {
            __syncthreads();
            if (tid == 0) {
                __threadfence();
                atomicAdd(&g_bar, 1u);
                const unsigned target = (unsigned)NCTA * (unsigned)(t + 1);
                unsigned v;
                do {
                    asm volatile("ld.global.acquire.gpu.u32 %0, [%1];"
                                 : "=r"(v) : "l"(&g_bar));
                    if (v < target) __nanosleep(32);
                } while (v < target);
            }
            __syncthreads();
        }
    }
}

// ---------------------------------------------------------------------------
// Finalize: hy = outputs[T-1], cy = g_c
// ---------------------------------------------------------------------------
__global__ void finalize_kernel(float* __restrict__ out)
{
    int i = blockIdx.x * blockDim.x + threadIdx.x;
    const size_t TBH = (size_t)TT * BB * HH;
    out[TBH + i]                   = out[TBH - (size_t)BB * HH + i];
    out[TBH + (size_t)BB * HH + i] = g_c[i];
}

// ---------------------------------------------------------------------------
extern "C" void kernel_launch(void* const* d_in, const int* in_sizes, int n_in,
                              void* d_out, int out_size)
{
    const float* X    = (const float*)d_in[0];
    const float* hx   = (const float*)d_in[1];
    const float* cx   = (const float*)d_in[2];
    const float* w_ii = (const float*)d_in[3];
    const float* w_fi = (const float*)d_in[4];
    const float* w_ai = (const float*)d_in[5];
    const float* w_oi = (const float*)d_in[6];
    const float* w_ih = (const float*)d_in[7];
    const float* w_fh = (const float*)d_in[8];
    const float* w_ah = (const float*)d_in[9];
    const float* w_oh = (const float*)d_in[10];
    const float* b_i  = (const float*)d_in[11];
    const float* b_f  = (const float*)d_in[12];
    const float* b_a  = (const float*)d_in[13];
    const float* b_o  = (const float*)d_in[14];
    float* out = (float*)d_out;

    (void)in_sizes; (void)n_in; (void)out_size;

    cudaFuncSetAttribute(proj_hmma_kernel,
                         cudaFuncAttributeMaxDynamicSharedMemorySize, PSMEM);
    cudaFuncSetAttribute(lstm_persist_kernel,
                         cudaFuncAttributeMaxDynamicSharedMemorySize, SMEM_TOTAL);

    // Prep: splits + bias + h0 + barrier reset
    prep_wh<<<N4H, 256>>>(w_ih, w_fh, w_ah, w_oh);
    prep_wi<<<N4H, 256>>>(w_ii, w_fi, w_ai, w_oi);
    prep_bias<<<N4H / 256, 256>>>(b_i, b_f, b_a, b_o);
    prep_x<<<(int)((size_t)MTOT * II / 4 / 256), 256>>>(X);
    prep_h<<<(BB * HH) / 256, 256>>>(hx);

    // Input projections on tensor cores
    dim3 pg(N4H / 128, MTOT / 128);   // (32, 256)
    proj_hmma_kernel<<<pg, 512, PSMEM>>>();

    // All 512 recurrent steps, one persistent launch
    lstm_persist_kernel<<<NCTA, 512, SMEM_TOTAL>>>(cx, out);

    finalize_kernel<<<(BB * HH) / 256, 256>>>(out);
}